// round 15
// baseline (speedup 1.0000x reference)
#include <cuda_runtime.h>
#include <cuda_bf16.h>
#include <mma.h>
#include <cstdint>
#include <math.h>
using namespace nvcuda;
typedef __nv_bfloat16 bf16;

#define BS 2
#define DD 512
#define NN 65536
#define RR 64
#define EPSF 1e-6f

// ---------- device scratch ----------
__device__ __align__(16) bf16 g_xu_h[(size_t)BS*DD*NN], g_xu_l[(size_t)BS*DD*NN]; // x unclamped [d][n]
__device__ __align__(16) bf16 g_xc_h[(size_t)BS*DD*NN], g_xc_l[(size_t)BS*DD*NN]; // x clamped   [d][n]
__device__ __align__(16) bf16 g_ct_h[(size_t)BS*RR*NN], g_ct_l[(size_t)BS*RR*NN]; // c'^T [r][n]
__device__ __align__(16) bf16 g_cn_h[(size_t)BS*NN*RR], g_cn_l[(size_t)BS*NN*RR]; // c_new [n][r]
__device__ __align__(16) bf16 g_bt_h[BS*RR*DD], g_bt_l[BS*RR*DD];                 // b^T [r][d]
__device__ __align__(16) bf16 g_bn_h[BS*DD*RR], g_bn_l[BS*DD*RR];                 // b [d][r]
__device__ __align__(16) float g_c[(size_t)BS*NN*RR];
__device__ float g_b0[BS*DD*RR], g_b1[BS*DD*RR];
__device__ float g_BtB[BS*RR*RR], g_CtC[BS*RR*RR], g_numB[BS*DD*RR];
__device__ __forceinline__ float* bsel(int s){ return s ? g_b1 : g_b0; }

__device__ __forceinline__ void split2(float v, unsigned short& h, unsigned short& l){
    bf16 hb = __float2bfloat16_rn(v);
    bf16 lb = __float2bfloat16_rn(v - __bfloat162float(hb));
    h = __bfloat16_as_ushort(hb); l = __bfloat16_as_ushort(lb);
}
__device__ __forceinline__ uint32_t pk(unsigned short a, unsigned short b){ return (uint32_t)a | ((uint32_t)b << 16); }
__device__ __forceinline__ uint32_t smem_u32(const void* p){
    uint32_t a; asm("{ .reg .u64 t; cvta.to.shared.u64 t, %1; cvt.u32.u64 %0, t; }" : "=r"(a) : "l"(p)); return a;
}
__device__ __forceinline__ void cpa16(uint32_t s, const void* g){
    asm volatile("cp.async.cg.shared.global [%0], [%1], 16;" :: "r"(s), "l"(g) : "memory");
}
#define CPCOMMIT() asm volatile("cp.async.commit_group;" ::: "memory")
#define CPWAIT2()  asm volatile("cp.async.wait_group 2;" ::: "memory")

// smem: A stages 3x20480 @0..61440, B stages 3x10240 @61440..92160. SMEMG = 92160.
// post-mainloop overlays: Ct f32[128][76] @0 (38912), BtB @40960 (16384), csm f32[128][65] @57344 (33280)
#define AST(st) ((st)*20480)
#define BST(st) (61440 + (st)*10240)
#define BT_OFF  40960
#define CSM_OFF 57344
#define SMEMG 92160
#define CTS 76   // Ct stride: multiple of 4 (WMMA ldm requirement)

typedef wmma::fragment<wmma::accumulator,16,16,16,float> AccFrag;
typedef wmma::fragment<wmma::matrix_a,16,16,16,bf16,wmma::row_major> AFragR;
typedef wmma::fragment<wmma::matrix_a,16,16,16,bf16,wmma::col_major> AFragC;
typedef wmma::fragment<wmma::matrix_b,16,16,16,bf16,wmma::col_major> BFragC;

template<bool ACOL>
__device__ __forceinline__ void issue_chunk(uint32_t sb, int st,
    const bf16* __restrict__ Ah, const bf16* __restrict__ Al, size_t lda,
    const bf16* __restrict__ Bh, const bf16* __restrict__ Bl, size_t ldb, size_t k0)
{
    int t = threadIdx.x;
    uint32_t ab = sb + AST(st), bb = sb + BST(st);
    if (ACOL){ // 32 k-rows x 128 m, smem stride 136
        #pragma unroll
        for (int u = 0; u < 2; u++){
            int idx = t + u*256, r = idx >> 4, sg = (idx & 15)*8;
            cpa16(ab +        (r*136 + sg)*2, Ah + (k0+r)*lda + sg);
            cpa16(ab + 8704 + (r*136 + sg)*2, Al + (k0+r)*lda + sg);
        }
    } else {   // 128 m-rows x 32 k, smem stride 40
        #pragma unroll
        for (int u = 0; u < 2; u++){
            int idx = t + u*256, r = idx >> 2, sg = (idx & 3)*8;
            cpa16(ab +         (r*40 + sg)*2, Ah + r*lda + k0 + sg);
            cpa16(ab + 10240 + (r*40 + sg)*2, Al + r*lda + k0 + sg);
        }
    }
    { int r = t >> 2, sg = (t & 3)*8;
      cpa16(bb +        (r*40 + sg)*2, Bh + r*ldb + k0 + sg);
      cpa16(bb + 5120 + (r*40 + sg)*2, Bl + r*ldb + k0 + sg);
    }
    CPCOMMIT();
}

template<bool ACOL>
__device__ __forceinline__ void gemm_core(
    const bf16* __restrict__ Ah, const bf16* __restrict__ Al, size_t lda,
    const bf16* __restrict__ Bh, const bf16* __restrict__ Bl, size_t ldb,
    int kchunks, char* sm, uint32_t sb, AccFrag (&acc)[2][2])
{
    int wid = threadIdx.x >> 5, wm = wid >> 1, wn = wid & 1;
    #pragma unroll
    for (int i = 0; i < 2; i++)
        #pragma unroll
        for (int j = 0; j < 2; j++) wmma::fill_fragment(acc[i][j], 0.0f);
    #pragma unroll
    for (int p = 0; p < 3; p++){
        if (p < kchunks) issue_chunk<ACOL>(sb, p, Ah, Al, lda, Bh, Bl, ldb, (size_t)p*32);
        else CPCOMMIT();
    }
    for (int kc = 0; kc < kchunks; kc++){
        CPWAIT2();                 // committed = 3+kc; groups 0..kc complete
        __syncthreads();
        int cur = kc % 3;
        bf16* As = (bf16*)(sm + AST(cur));
        bf16* Bs = (bf16*)(sm + BST(cur));
        #pragma unroll
        for (int k = 0; k < 2; k++){
            BFragC fbh[2], fbl[2];
            #pragma unroll
            for (int j = 0; j < 2; j++){
                wmma::load_matrix_sync(fbh[j], Bs + (wn*32+j*16)*40 + k*16, 40);
                wmma::load_matrix_sync(fbl[j], Bs + 2560 + (wn*32+j*16)*40 + k*16, 40);
            }
            if (ACOL){
                AFragC fah[2], fal[2];
                #pragma unroll
                for (int i = 0; i < 2; i++){
                    wmma::load_matrix_sync(fah[i], As + (k*16)*136 + wm*32+i*16, 136);
                    wmma::load_matrix_sync(fal[i], As + 4352 + (k*16)*136 + wm*32+i*16, 136);
                }
                #pragma unroll
                for (int i = 0; i < 2; i++)
                    #pragma unroll
                    for (int j = 0; j < 2; j++){
                        wmma::mma_sync(acc[i][j], fah[i], fbh[j], acc[i][j]);
                        wmma::mma_sync(acc[i][j], fah[i], fbl[j], acc[i][j]);
                        wmma::mma_sync(acc[i][j], fal[i], fbh[j], acc[i][j]);
                    }
            } else {
                AFragR fah[2], fal[2];
                #pragma unroll
                for (int i = 0; i < 2; i++){
                    wmma::load_matrix_sync(fah[i], As + (wm*32+i*16)*40 + k*16, 40);
                    wmma::load_matrix_sync(fal[i], As + 5120 + (wm*32+i*16)*40 + k*16, 40);
                }
                #pragma unroll
                for (int i = 0; i < 2; i++)
                    #pragma unroll
                    for (int j = 0; j < 2; j++){
                        wmma::mma_sync(acc[i][j], fah[i], fbh[j], acc[i][j]);
                        wmma::mma_sync(acc[i][j], fah[i], fbl[j], acc[i][j]);
                        wmma::mma_sync(acc[i][j], fal[i], fbh[j], acc[i][j]);
                    }
            }
        }
        __syncthreads();           // stage cur consumed
        if (kc + 3 < kchunks) issue_chunk<ACOL>(sb, cur, Ah, Al, lda, Bh, Bl, ldb, (size_t)(kc+3)*32);
        else CPCOMMIT();
    }
}

__device__ __forceinline__ void store_acc(char* sm, AccFrag (&acc)[2][2], int ldm){
    float* Ct = (float*)sm;
    int wid = threadIdx.x >> 5, wm = wid >> 1, wn = wid & 1;
    #pragma unroll
    for (int i = 0; i < 2; i++)
        #pragma unroll
        for (int j = 0; j < 2; j++)
            wmma::store_matrix_sync(Ct + (wm*32+i*16)*ldm + wn*32+j*16, acc[i][j], ldm, wmma::mem_row_major);
}

// ---------- prep ----------
__global__ void __launch_bounds__(256) k_prep(const float* __restrict__ x){
    size_t base = ((size_t)blockIdx.x*256 + threadIdx.x)*16;
    #pragma unroll
    for (int q = 0; q < 4; q++){
        size_t o = base + q*4;
        float4 v = *(const float4*)(x + o);
        unsigned short h[4], l[4];
        split2(v.x,h[0],l[0]); split2(v.y,h[1],l[1]); split2(v.z,h[2],l[2]); split2(v.w,h[3],l[3]);
        *(uint2*)(g_xu_h + o) = make_uint2(pk(h[0],h[1]), pk(h[2],h[3]));
        *(uint2*)(g_xu_l + o) = make_uint2(pk(l[0],l[1]), pk(l[2],l[3]));
        split2(fmaxf(v.x,EPSF),h[0],l[0]); split2(fmaxf(v.y,EPSF),h[1],l[1]);
        split2(fmaxf(v.z,EPSF),h[2],l[2]); split2(fmaxf(v.w,EPSF),h[3],l[3]);
        *(uint2*)(g_xc_h + o) = make_uint2(pk(h[0],h[1]), pk(h[2],h[3]));
        *(uint2*)(g_xc_l + o) = make_uint2(pk(l[0],l[1]), pk(l[2],l[3]));
    }
}

__global__ void __launch_bounds__(128) k_normb(const float* __restrict__ bases){
    int bs = blockIdx.x >> 6, r = blockIdx.x & 63, tid = threadIdx.x;
    __shared__ float red[128];
    float s = 0.f;
    for (int d = tid; d < DD; d += 128){ float v = bases[(bs*DD+d)*RR + r]; s += v*v; }
    red[tid] = s; __syncthreads();
    for (int o = 64; o > 0; o >>= 1){ if (tid < o) red[tid] += red[tid+o]; __syncthreads(); }
    float inv = 1.f / fmaxf(sqrtf(red[0]), 1e-12f);
    for (int d = tid; d < DD; d += 128){
        float v = bases[(bs*DD+d)*RR + r] * inv;
        g_b0[(bs*DD+d)*RR + r] = v;
        unsigned short h, l; split2(v, h, l);
        g_bt_h[(bs*RR+r)*DD + d] = __ushort_as_bfloat16(h);
        g_bt_l[(bs*RR+r)*DD + d] = __ushort_as_bfloat16(l);
    }
}

// zero ALL accumulators (once per replay, before first k_btb)
__global__ void k_zero(){
    int i = blockIdx.x*256 + threadIdx.x;
    if (i < BS*RR*RR){ g_BtB[i] = 0.f; g_CtC[i] = 0.f; }
    if (i < BS*DD*RR) g_numB[i] = 0.f;
}

// BtB: grid (8, BS), smem staging + atomic combine (requires pre-zeroed BtB)
__global__ void __launch_bounds__(256) k_btb(int sel){
    __shared__ float bsh[64][65];
    int bs = blockIdx.y, d0 = blockIdx.x*64, tid = threadIdx.x;
    const float* bb = bsel(sel) + bs*DD*RR + d0*RR;
    for (int i = tid*4; i < 4096; i += 1024){
        float4 v = *(const float4*)(bb + i);
        int d = i >> 6, r = i & 63;
        bsh[d][r]=v.x; bsh[d][r+1]=v.y; bsh[d][r+2]=v.z; bsh[d][r+3]=v.w;
    }
    __syncthreads();
    int r = tid & 63, sq = (tid >> 6)*16;
    float acc[16];
    #pragma unroll
    for (int j = 0; j < 16; j++) acc[j] = 0.f;
    for (int d = 0; d < 64; d++){
        float br = bsh[d][r];
        #pragma unroll
        for (int j = 0; j < 16; j++) acc[j] = fmaf(br, bsh[d][sq+j], acc[j]);
    }
    float* o = g_BtB + bs*RR*RR + r*RR + sq;
    #pragma unroll
    for (int j = 0; j < 16; j++) atomicAdd(&o[j], acc[j]);
}

// ---------- fused c kernel: MODE 0 init softmax, 1 MU step, 2 final ----------
template<int MODE>
__global__ void __launch_bounds__(256, 2) k_cmma(int clampc){
    extern __shared__ char sm[];
    uint32_t sb = smem_u32(sm);
    int bs = blockIdx.y, n0 = blockIdx.x*128, tid = threadIdx.x;
    const bf16* xh = (MODE==0 ? g_xu_h : g_xc_h) + (size_t)bs*DD*NN + n0;
    const bf16* xl = (MODE==0 ? g_xu_l : g_xc_l) + (size_t)bs*DD*NN + n0;

    AccFrag acc[2][2];
    gemm_core<true>(xh, xl, NN, g_bt_h + bs*RR*DD, g_bt_l + bs*RR*DD, DD, 16, sm, sb, acc);
    __syncthreads();                 // stages dead; overlays usable
    store_acc(sm, acc, CTS);
    float* Ct  = (float*)sm;
    float* Bt  = (float*)(sm + BT_OFF);
    float* csm = (float*)(sm + CSM_OFF);
    if (MODE != 0){
        for (int i = tid; i < RR*RR; i += 256) Bt[i] = g_BtB[bs*RR*RR + i];
        size_t cbase = ((size_t)bs*NN + n0)*RR;
        for (int i = tid; i < 2048; i += 256){
            int n = i >> 4, r4 = (i & 15)*4;
            float4 v = *(const float4*)(g_c + cbase + n*RR + r4);
            if (clampc){ v.x=fmaxf(v.x,EPSF); v.y=fmaxf(v.y,EPSF); v.z=fmaxf(v.z,EPSF); v.w=fmaxf(v.w,EPSF); }
            csm[n*65+r4]=v.x; csm[n*65+r4+1]=v.y; csm[n*65+r4+2]=v.z; csm[n*65+r4+3]=v.w;
        }
    }
    __syncthreads();

    int n = tid >> 1, h = tid & 1;
    size_t crow = ((size_t)bs*NN + n0 + n)*RR;
    if (MODE == 0){
        float v[32], m = -1e30f;
        #pragma unroll
        for (int j = 0; j < 32; j++){ v[j] = Ct[n*CTS + h*32 + j]; m = fmaxf(m, v[j]); }
        m = fmaxf(m, __shfl_xor_sync(0xffffffffu, m, 1));
        float s = 0.f;
        #pragma unroll
        for (int j = 0; j < 32; j++){ v[j] = __expf(v[j]-m); s += v[j]; }
        s += __shfl_xor_sync(0xffffffffu, s, 1);
        float inv = 1.f/s;
        #pragma unroll
        for (int j4 = 0; j4 < 32; j4 += 4)
            *(float4*)(g_c + crow + h*32 + j4) = make_float4(v[j4]*inv, v[j4+1]*inv, v[j4+2]*inv, v[j4+3]*inv);
        return;
    }
    float den[32];
    #pragma unroll
    for (int j = 0; j < 32; j++) den[j] = 0.f;
    #pragma unroll 8
    for (int s = 0; s < 64; s++){
        float cv = csm[n*65 + s];
        const float* row = &Bt[s*64 + h*32];
        #pragma unroll
        for (int j = 0; j < 32; j++) den[j] = fmaf(cv, row[j], den[j]);
    }
    #pragma unroll
    for (int j4 = 0; j4 < 32; j4 += 4){
        float cp[4];
        #pragma unroll
        for (int t = 0; t < 4; t++){
            int j = j4 + t;
            cp[t] = csm[n*65 + h*32 + j] * Ct[n*CTS + h*32 + j] / (den[j] + EPSF);
            Ct[n*CTS + h*32 + j] = cp[t];
        }
        if (MODE == 1)
            *(float4*)(g_c + crow + h*32 + j4) = make_float4(cp[0], cp[1], cp[2], cp[3]);
        else {
            unsigned short hh[4], ll[4];
            #pragma unroll
            for (int t = 0; t < 4; t++) split2(cp[t], hh[t], ll[t]);
            size_t o = crow + h*32 + j4;
            *(uint2*)(g_cn_h + o) = make_uint2(pk(hh[0],hh[1]), pk(hh[2],hh[3]));
            *(uint2*)(g_cn_l + o) = make_uint2(pk(ll[0],ll[1]), pk(ll[2],ll[3]));
        }
    }
    if (MODE == 2) return;
    __syncthreads();   // Ct holds full c'

    // coalesced c'^T split writes: warp w handles rows r = w*8..w*8+7, lanes span n
    {
        int w = tid >> 5, l = tid & 31;
        #pragma unroll
        for (int i = 0; i < 8; i++){
            int r = w*8 + i;
            size_t orow = ((size_t)bs*RR + r)*NN + n0;
            #pragma unroll
            for (int j = 0; j < 4; j++){
                int nn2 = j*32 + l;
                unsigned short hh, llx;
                split2(Ct[nn2*CTS + r], hh, llx);
                g_ct_h[orow + nn2] = __ushort_as_bfloat16(hh);
                g_ct_l[orow + nn2] = __ushort_as_bfloat16(llx);
            }
        }
    }
    // CtC partials
    {
        int r = tid & 63, q = tid >> 6;
        float ctc[16];
        #pragma unroll
        for (int j = 0; j < 16; j++) ctc[j] = 0.f;
        for (int nn2 = 0; nn2 < 128; nn2++){
            float cr = Ct[nn2*CTS + r];
            const float* row = &Ct[nn2*CTS + q*16];
            #pragma unroll
            for (int j = 0; j < 16; j++) ctc[j] = fmaf(cr, row[j], ctc[j]);
        }
        float* gout = g_CtC + bs*RR*RR + r*RR + q*16;
        #pragma unroll
        for (int j = 0; j < 16; j++) atomicAdd(&gout[j], ctc[j]);
    }
}

// ---------- numB: split-K over N (128 blocks of 512 n -> full waves) ----------
__global__ void __launch_bounds__(256, 2) k_numBmma(){
    extern __shared__ char sm[];
    uint32_t sb = smem_u32(sm);
    int bs = blockIdx.z, d0 = blockIdx.y*128, tid = threadIdx.x;
    size_t nb = (size_t)blockIdx.x * 512;
    AccFrag acc[2][2];
    gemm_core<false>(g_xc_h + ((size_t)bs*DD + d0)*NN + nb, g_xc_l + ((size_t)bs*DD + d0)*NN + nb, NN,
                     g_ct_h + (size_t)bs*RR*NN + nb,        g_ct_l + (size_t)bs*RR*NN + nb,        NN,
                     16, sm, sb, acc);
    __syncthreads();
    store_acc(sm, acc, 72);
    __syncthreads();
    float* Ct = (float*)sm;
    int d = tid >> 1, h = tid & 1;
    float* out = g_numB + (bs*DD + d0 + d)*RR + h*32;
    #pragma unroll
    for (int j = 0; j < 32; j++) atomicAdd(&out[j], Ct[d*72 + h*32 + j]);
}

// ---------- b update (also zeroes consumed accumulators for next step) ----------
__global__ void __launch_bounds__(128) k_bupdate(int selIn, int selOut){
    int r = blockIdx.x, bs = blockIdx.y, tid = threadIdx.x;
    __shared__ float ctcCol[64], red[128];
    const float* bin = bsel(selIn) + bs*DD*RR;
    float* bout = bsel(selOut) + bs*DD*RR;
    float* nb = g_numB + bs*DD*RR;
    if (tid < 64) ctcCol[tid] = g_CtC[bs*RR*RR + tid*RR + r];
    __syncthreads();
    float v[4], ss = 0.f;
    #pragma unroll
    for (int q = 0; q < 4; q++){
        int d = tid + q*128; const float* brow = bin + d*RR;
        float den = EPSF;
        #pragma unroll 8
        for (int s = 0; s < RR; s++) den = fmaf(brow[s], ctcCol[s], den);
        float t = fmaxf(brow[r] * nb[d*RR + r] / den, EPSF);
        v[q] = t; ss += t*t;
        nb[d*RR + r] = 0.f;
    }
    red[tid] = ss; __syncthreads();
    for (int o = 64; o > 0; o >>= 1){ if (tid < o) red[tid] += red[tid+o]; __syncthreads(); }
    float inv = 1.f / fmaxf(sqrtf(red[0]), 1e-12f);
    #pragma unroll
    for (int q = 0; q < 4; q++){
        int d = tid + q*128;
        float w = v[q] * inv;
        bout[d*RR + r] = w;
        unsigned short h, l; split2(w, h, l);
        g_bt_h[(bs*RR+r)*DD + d] = __ushort_as_bfloat16(h);
        g_bt_l[(bs*RR+r)*DD + d] = __ushort_as_bfloat16(l);
        g_bn_h[(bs*DD+d)*RR + r] = __ushort_as_bfloat16(h);
        g_bn_l[(bs*DD+d)*RR + r] = __ushort_as_bfloat16(l);
    }
    if (tid < 64){
        g_CtC[bs*RR*RR + tid*RR + r] = 0.f;
        g_BtB[bs*RR*RR + r*64 + tid] = 0.f;
    }
}

// ---------- x_hat ----------
__global__ void __launch_bounds__(256, 2) k_xhat(float* __restrict__ out){
    extern __shared__ char sm[];
    uint32_t sb = smem_u32(sm);
    int bs = blockIdx.z, d0 = blockIdx.y*128, n0 = blockIdx.x*64, tid = threadIdx.x;
    AccFrag acc[2][2];
    gemm_core<false>(g_bn_h + (bs*DD + d0)*RR,         g_bn_l + (bs*DD + d0)*RR,         RR,
                     g_cn_h + ((size_t)bs*NN + n0)*RR, g_cn_l + ((size_t)bs*NN + n0)*RR, RR,
                     2, sm, sb, acc);
    __syncthreads();
    store_acc(sm, acc, 72);
    __syncthreads();
    float* Ct = (float*)sm;
    int d = tid >> 1, h = tid & 1;
    float* orow = out + (size_t)(bs*DD + d0 + d)*NN + n0 + h*32;
    #pragma unroll
    for (int j4 = 0; j4 < 32; j4 += 4)
        *(float4*)(orow + j4) = make_float4(Ct[d*72+h*32+j4], Ct[d*72+h*32+j4+1], Ct[d*72+h*32+j4+2], Ct[d*72+h*32+j4+3]);
}

// ---------- orchestration ----------
extern "C" void kernel_launch(void* const* d_in, const int* in_sizes, int n_in,
                              void* d_out, int out_size){
    const float* x = (const float*)d_in[0];
    const float* bases = (const float*)d_in[1];
    float* out = (float*)d_out;

    cudaFuncSetAttribute(k_cmma<0>, cudaFuncAttributeMaxDynamicSharedMemorySize, SMEMG);
    cudaFuncSetAttribute(k_cmma<1>, cudaFuncAttributeMaxDynamicSharedMemorySize, SMEMG);
    cudaFuncSetAttribute(k_cmma<2>, cudaFuncAttributeMaxDynamicSharedMemorySize, SMEMG);
    cudaFuncSetAttribute(k_numBmma, cudaFuncAttributeMaxDynamicSharedMemorySize, SMEMG);
    cudaFuncSetAttribute(k_xhat,    cudaFuncAttributeMaxDynamicSharedMemorySize, SMEMG);

    k_normb<<<BS*RR, 128>>>(bases);
    k_prep<<<16384, 256>>>(x);
    k_zero<<<256, 256>>>();
    k_btb<<<dim3(8, BS), 256>>>(0);
    k_cmma<0><<<dim3(NN/128, BS), 256, SMEMG>>>(0);
    int sel = 0;
    for (int step = 0; step < 6; step++){
        k_cmma<1><<<dim3(NN/128, BS), 256, SMEMG>>>(step > 0 ? 1 : 0);
        k_numBmma<<<dim3(128, DD/128, BS), 256, SMEMG>>>();
        k_bupdate<<<dim3(RR, BS), 128>>>(sel, 1 - sel);
        sel = 1 - sel;
        k_btb<<<dim3(8, BS), 256>>>(sel);
    }
    k_cmma<2><<<dim3(NN/128, BS), 256, SMEMG>>>(1);
    k_xhat<<<dim3(NN/64, DD/128, BS), 256, SMEMG>>>(out);
}

// round 16
// speedup vs baseline: 1.0768x; 1.0768x over previous
#include <cuda_runtime.h>
#include <cuda_bf16.h>
#include <mma.h>
#include <cstdint>
#include <math.h>
using namespace nvcuda;
typedef __nv_bfloat16 bf16;

#define BS 2
#define DD 512
#define NN 65536
#define RR 64
#define EPSF 1e-6f

// ---------- device scratch ----------
__device__ __align__(16) bf16 g_xu_h[(size_t)BS*DD*NN], g_xu_l[(size_t)BS*DD*NN]; // x unclamped [d][n]
__device__ __align__(16) bf16 g_xc_h[(size_t)BS*DD*NN], g_xc_l[(size_t)BS*DD*NN]; // x clamped   [d][n]
__device__ __align__(16) bf16 g_ct_h[(size_t)BS*NN*RR], g_ct_l[(size_t)BS*NN*RR]; // c' splits [n][r]
__device__ __align__(16) bf16 g_cn_h[(size_t)BS*NN*RR], g_cn_l[(size_t)BS*NN*RR]; // c_new [n][r]
__device__ __align__(16) bf16 g_bt_h[BS*RR*DD], g_bt_l[BS*RR*DD];                 // b^T [r][d]
__device__ __align__(16) bf16 g_bn_h[BS*DD*RR], g_bn_l[BS*DD*RR];                 // b [d][r]
__device__ __align__(16) float g_c[(size_t)BS*NN*RR];
__device__ float g_b0[BS*DD*RR], g_b1[BS*DD*RR];
__device__ float g_BtB[BS*RR*RR], g_CtC[BS*RR*RR], g_numB[BS*DD*RR];
__device__ __forceinline__ float* bsel(int s){ return s ? g_b1 : g_b0; }

__device__ __forceinline__ void split2(float v, unsigned short& h, unsigned short& l){
    bf16 hb = __float2bfloat16_rn(v);
    bf16 lb = __float2bfloat16_rn(v - __bfloat162float(hb));
    h = __bfloat16_as_ushort(hb); l = __bfloat16_as_ushort(lb);
}
__device__ __forceinline__ uint32_t pk(unsigned short a, unsigned short b){ return (uint32_t)a | ((uint32_t)b << 16); }
__device__ __forceinline__ uint32_t smem_u32(const void* p){
    uint32_t a; asm("{ .reg .u64 t; cvta.to.shared.u64 t, %1; cvt.u32.u64 %0, t; }" : "=r"(a) : "l"(p)); return a;
}
__device__ __forceinline__ void cpa16(uint32_t s, const void* g){
    asm volatile("cp.async.cg.shared.global [%0], [%1], 16;" :: "r"(s), "l"(g) : "memory");
}
#define CPCOMMIT() asm volatile("cp.async.commit_group;" ::: "memory")
#define CPWAIT1()  asm volatile("cp.async.wait_group 1;" ::: "memory")
#define CPWAIT2()  asm volatile("cp.async.wait_group 2;" ::: "memory")

// cmma smem: A stages 3x20480 @0..61440, B stages 3x10240 @61440..92160. SMEMG = 92160.
// overlays: Ct f32[128][76] @0 (38912), BtB @40960 (16384), csm f32[128][65] @57344 (33280)
#define AST(st) ((st)*20480)
#define BST(st) (61440 + (st)*10240)
#define BT_OFF  40960
#define CSM_OFF 57344
#define SMEMG 92160
#define CTS 76

// numB smem: 2 stages x 55296 (A_h 18432 | A_l 18432 | B_h 9216 | B_l 9216). SMEMN = 110592.
#define NST(st) ((st)*55296)
#define SMEMN 110592

typedef wmma::fragment<wmma::accumulator,16,16,16,float> AccFrag;
typedef wmma::fragment<wmma::matrix_a,16,16,16,bf16,wmma::row_major> AFragR;
typedef wmma::fragment<wmma::matrix_a,16,16,16,bf16,wmma::col_major> AFragC;
typedef wmma::fragment<wmma::matrix_b,16,16,16,bf16,wmma::row_major> BFragR;
typedef wmma::fragment<wmma::matrix_b,16,16,16,bf16,wmma::col_major> BFragC;

// ---- cmma/xhat chunk loader (32-k chunks) ----
template<bool ACOL>
__device__ __forceinline__ void issue_chunk(uint32_t sb, int st,
    const bf16* __restrict__ Ah, const bf16* __restrict__ Al, size_t lda,
    const bf16* __restrict__ Bh, const bf16* __restrict__ Bl, size_t ldb, size_t k0)
{
    int t = threadIdx.x;
    uint32_t ab = sb + AST(st), bb = sb + BST(st);
    if (ACOL){ // 32 k-rows x 128 m, stride 136
        #pragma unroll
        for (int u = 0; u < 2; u++){
            int idx = t + u*256, r = idx >> 4, sg = (idx & 15)*8;
            cpa16(ab +        (r*136 + sg)*2, Ah + (k0+r)*lda + sg);
            cpa16(ab + 8704 + (r*136 + sg)*2, Al + (k0+r)*lda + sg);
        }
    } else {   // 128 m-rows x 32 k, stride 40
        #pragma unroll
        for (int u = 0; u < 2; u++){
            int idx = t + u*256, r = idx >> 2, sg = (idx & 3)*8;
            cpa16(ab +         (r*40 + sg)*2, Ah + r*lda + k0 + sg);
            cpa16(ab + 10240 + (r*40 + sg)*2, Al + r*lda + k0 + sg);
        }
    }
    { int r = t >> 2, sg = (t & 3)*8;
      cpa16(bb +        (r*40 + sg)*2, Bh + r*ldb + k0 + sg);
      cpa16(bb + 5120 + (r*40 + sg)*2, Bl + r*ldb + k0 + sg);
    }
    CPCOMMIT();
}

template<bool ACOL>
__device__ __forceinline__ void gemm_core(
    const bf16* __restrict__ Ah, const bf16* __restrict__ Al, size_t lda,
    const bf16* __restrict__ Bh, const bf16* __restrict__ Bl, size_t ldb,
    int kchunks, char* sm, uint32_t sb, AccFrag (&acc)[2][2])
{
    int wid = threadIdx.x >> 5, wm = wid >> 1, wn = wid & 1;
    #pragma unroll
    for (int i = 0; i < 2; i++)
        #pragma unroll
        for (int j = 0; j < 2; j++) wmma::fill_fragment(acc[i][j], 0.0f);
    #pragma unroll
    for (int p = 0; p < 3; p++){
        if (p < kchunks) issue_chunk<ACOL>(sb, p, Ah, Al, lda, Bh, Bl, ldb, (size_t)p*32);
        else CPCOMMIT();
    }
    for (int kc = 0; kc < kchunks; kc++){
        CPWAIT2();
        __syncthreads();
        int cur = kc % 3;
        bf16* As = (bf16*)(sm + AST(cur));
        bf16* Bs = (bf16*)(sm + BST(cur));
        #pragma unroll
        for (int k = 0; k < 2; k++){
            BFragC fbh[2], fbl[2];
            #pragma unroll
            for (int j = 0; j < 2; j++){
                wmma::load_matrix_sync(fbh[j], Bs + (wn*32+j*16)*40 + k*16, 40);
                wmma::load_matrix_sync(fbl[j], Bs + 2560 + (wn*32+j*16)*40 + k*16, 40);
            }
            if (ACOL){
                AFragC fah[2], fal[2];
                #pragma unroll
                for (int i = 0; i < 2; i++){
                    wmma::load_matrix_sync(fah[i], As + (k*16)*136 + wm*32+i*16, 136);
                    wmma::load_matrix_sync(fal[i], As + 4352 + (k*16)*136 + wm*32+i*16, 136);
                }
                #pragma unroll
                for (int i = 0; i < 2; i++)
                    #pragma unroll
                    for (int j = 0; j < 2; j++){
                        wmma::mma_sync(acc[i][j], fah[i], fbh[j], acc[i][j]);
                        wmma::mma_sync(acc[i][j], fah[i], fbl[j], acc[i][j]);
                        wmma::mma_sync(acc[i][j], fal[i], fbh[j], acc[i][j]);
                    }
            } else {
                AFragR fah[2], fal[2];
                #pragma unroll
                for (int i = 0; i < 2; i++){
                    wmma::load_matrix_sync(fah[i], As + (wm*32+i*16)*40 + k*16, 40);
                    wmma::load_matrix_sync(fal[i], As + 5120 + (wm*32+i*16)*40 + k*16, 40);
                }
                #pragma unroll
                for (int i = 0; i < 2; i++)
                    #pragma unroll
                    for (int j = 0; j < 2; j++){
                        wmma::mma_sync(acc[i][j], fah[i], fbh[j], acc[i][j]);
                        wmma::mma_sync(acc[i][j], fah[i], fbl[j], acc[i][j]);
                        wmma::mma_sync(acc[i][j], fal[i], fbh[j], acc[i][j]);
                    }
            }
        }
        __syncthreads();
        if (kc + 3 < kchunks) issue_chunk<ACOL>(sb, cur, Ah, Al, lda, Bh, Bl, ldb, (size_t)(kc+3)*32);
        else CPCOMMIT();
    }
}

__device__ __forceinline__ void store_acc(char* sm, AccFrag (&acc)[2][2], int ldm){
    float* Ct = (float*)sm;
    int wid = threadIdx.x >> 5, wm = wid >> 1, wn = wid & 1;
    #pragma unroll
    for (int i = 0; i < 2; i++)
        #pragma unroll
        for (int j = 0; j < 2; j++)
            wmma::store_matrix_sync(Ct + (wm*32+i*16)*ldm + wn*32+j*16, acc[i][j], ldm, wmma::mem_row_major);
}

// ---------- prep ----------
__global__ void __launch_bounds__(256) k_prep(const float* __restrict__ x){
    size_t base = ((size_t)blockIdx.x*256 + threadIdx.x)*16;
    #pragma unroll
    for (int q = 0; q < 4; q++){
        size_t o = base + q*4;
        float4 v = *(const float4*)(x + o);
        unsigned short h[4], l[4];
        split2(v.x,h[0],l[0]); split2(v.y,h[1],l[1]); split2(v.z,h[2],l[2]); split2(v.w,h[3],l[3]);
        *(uint2*)(g_xu_h + o) = make_uint2(pk(h[0],h[1]), pk(h[2],h[3]));
        *(uint2*)(g_xu_l + o) = make_uint2(pk(l[0],l[1]), pk(l[2],l[3]));
        split2(fmaxf(v.x,EPSF),h[0],l[0]); split2(fmaxf(v.y,EPSF),h[1],l[1]);
        split2(fmaxf(v.z,EPSF),h[2],l[2]); split2(fmaxf(v.w,EPSF),h[3],l[3]);
        *(uint2*)(g_xc_h + o) = make_uint2(pk(h[0],h[1]), pk(h[2],h[3]));
        *(uint2*)(g_xc_l + o) = make_uint2(pk(l[0],l[1]), pk(l[2],l[3]));
    }
}

__global__ void __launch_bounds__(128) k_normb(const float* __restrict__ bases){
    int bs = blockIdx.x >> 6, r = blockIdx.x & 63, tid = threadIdx.x;
    __shared__ float red[128];
    float s = 0.f;
    for (int d = tid; d < DD; d += 128){ float v = bases[(bs*DD+d)*RR + r]; s += v*v; }
    red[tid] = s; __syncthreads();
    for (int o = 64; o > 0; o >>= 1){ if (tid < o) red[tid] += red[tid+o]; __syncthreads(); }
    float inv = 1.f / fmaxf(sqrtf(red[0]), 1e-12f);
    for (int d = tid; d < DD; d += 128){
        float v = bases[(bs*DD+d)*RR + r] * inv;
        g_b0[(bs*DD+d)*RR + r] = v;
        unsigned short h, l; split2(v, h, l);
        g_bt_h[(bs*RR+r)*DD + d] = __ushort_as_bfloat16(h);
        g_bt_l[(bs*RR+r)*DD + d] = __ushort_as_bfloat16(l);
    }
}

__global__ void k_zero(){
    int i = blockIdx.x*256 + threadIdx.x;
    if (i < BS*RR*RR){ g_BtB[i] = 0.f; g_CtC[i] = 0.f; }
    if (i < BS*DD*RR) g_numB[i] = 0.f;
}

__global__ void __launch_bounds__(256) k_btb(int sel){
    __shared__ float bsh[64][65];
    int bs = blockIdx.y, d0 = blockIdx.x*64, tid = threadIdx.x;
    const float* bb = bsel(sel) + bs*DD*RR + d0*RR;
    for (int i = tid*4; i < 4096; i += 1024){
        float4 v = *(const float4*)(bb + i);
        int d = i >> 6, r = i & 63;
        bsh[d][r]=v.x; bsh[d][r+1]=v.y; bsh[d][r+2]=v.z; bsh[d][r+3]=v.w;
    }
    __syncthreads();
    int r = tid & 63, sq = (tid >> 6)*16;
    float acc[16];
    #pragma unroll
    for (int j = 0; j < 16; j++) acc[j] = 0.f;
    for (int d = 0; d < 64; d++){
        float br = bsh[d][r];
        #pragma unroll
        for (int j = 0; j < 16; j++) acc[j] = fmaf(br, bsh[d][sq+j], acc[j]);
    }
    float* o = g_BtB + bs*RR*RR + r*RR + sq;
    #pragma unroll
    for (int j = 0; j < 16; j++) atomicAdd(&o[j], acc[j]);
}

// ---------- fused c kernel: MODE 0 init softmax, 1 MU step, 2 final ----------
template<int MODE>
__global__ void __launch_bounds__(256, 2) k_cmma(int clampc){
    extern __shared__ char sm[];
    uint32_t sb = smem_u32(sm);
    int bs = blockIdx.y, n0 = blockIdx.x*128, tid = threadIdx.x;
    const bf16* xh = (MODE==0 ? g_xu_h : g_xc_h) + (size_t)bs*DD*NN + n0;
    const bf16* xl = (MODE==0 ? g_xu_l : g_xc_l) + (size_t)bs*DD*NN + n0;

    AccFrag acc[2][2];
    gemm_core<true>(xh, xl, NN, g_bt_h + bs*RR*DD, g_bt_l + bs*RR*DD, DD, 16, sm, sb, acc);
    __syncthreads();
    store_acc(sm, acc, CTS);
    float* Ct  = (float*)sm;
    float* Bt  = (float*)(sm + BT_OFF);
    float* csm = (float*)(sm + CSM_OFF);
    if (MODE != 0){
        for (int i = tid; i < RR*RR; i += 256) Bt[i] = g_BtB[bs*RR*RR + i];
        size_t cbase = ((size_t)bs*NN + n0)*RR;
        for (int i = tid; i < 2048; i += 256){
            int n = i >> 4, r4 = (i & 15)*4;
            float4 v = *(const float4*)(g_c + cbase + n*RR + r4);
            if (clampc){ v.x=fmaxf(v.x,EPSF); v.y=fmaxf(v.y,EPSF); v.z=fmaxf(v.z,EPSF); v.w=fmaxf(v.w,EPSF); }
            csm[n*65+r4]=v.x; csm[n*65+r4+1]=v.y; csm[n*65+r4+2]=v.z; csm[n*65+r4+3]=v.w;
        }
    }
    __syncthreads();

    int n = tid >> 1, h = tid & 1;
    size_t crow = ((size_t)bs*NN + n0 + n)*RR;
    if (MODE == 0){
        float v[32], m = -1e30f;
        #pragma unroll
        for (int j = 0; j < 32; j++){ v[j] = Ct[n*CTS + h*32 + j]; m = fmaxf(m, v[j]); }
        m = fmaxf(m, __shfl_xor_sync(0xffffffffu, m, 1));
        float s = 0.f;
        #pragma unroll
        for (int j = 0; j < 32; j++){ v[j] = __expf(v[j]-m); s += v[j]; }
        s += __shfl_xor_sync(0xffffffffu, s, 1);
        float inv = 1.f/s;
        #pragma unroll
        for (int j4 = 0; j4 < 32; j4 += 4)
            *(float4*)(g_c + crow + h*32 + j4) = make_float4(v[j4]*inv, v[j4+1]*inv, v[j4+2]*inv, v[j4+3]*inv);
        return;
    }
    float den[32];
    #pragma unroll
    for (int j = 0; j < 32; j++) den[j] = 0.f;
    #pragma unroll 8
    for (int s = 0; s < 64; s++){
        float cv = csm[n*65 + s];
        const float* row = &Bt[s*64 + h*32];
        #pragma unroll
        for (int j = 0; j < 32; j++) den[j] = fmaf(cv, row[j], den[j]);
    }
    #pragma unroll
    for (int j4 = 0; j4 < 32; j4 += 4){
        float cp[4];
        #pragma unroll
        for (int t = 0; t < 4; t++){
            int j = j4 + t;
            cp[t] = csm[n*65 + h*32 + j] * Ct[n*CTS + h*32 + j] / (den[j] + EPSF);
            Ct[n*CTS + h*32 + j] = cp[t];
        }
        unsigned short hh[4], ll[4];
        #pragma unroll
        for (int t = 0; t < 4; t++) split2(cp[t], hh[t], ll[t]);
        size_t o = crow + h*32 + j4;
        if (MODE == 1){
            *(float4*)(g_c + crow + h*32 + j4) = make_float4(cp[0], cp[1], cp[2], cp[3]);
            *(uint2*)(g_ct_h + o) = make_uint2(pk(hh[0],hh[1]), pk(hh[2],hh[3]));
            *(uint2*)(g_ct_l + o) = make_uint2(pk(ll[0],ll[1]), pk(ll[2],ll[3]));
        } else {
            *(uint2*)(g_cn_h + o) = make_uint2(pk(hh[0],hh[1]), pk(hh[2],hh[3]));
            *(uint2*)(g_cn_l + o) = make_uint2(pk(ll[0],ll[1]), pk(ll[2],ll[3]));
        }
    }
    if (MODE == 2) return;
    __syncthreads();   // Ct holds full c'
    // CtC partials (column reads, CTS=76 -> 4-way conflict)
    {
        int r = tid & 63, q = tid >> 6;
        float ctc[16];
        #pragma unroll
        for (int j = 0; j < 16; j++) ctc[j] = 0.f;
        for (int nn2 = 0; nn2 < 128; nn2++){
            float cr = Ct[nn2*CTS + r];
            const float* row = &Ct[nn2*CTS + q*16];
            #pragma unroll
            for (int j = 0; j < 16; j++) ctc[j] = fmaf(cr, row[j], ctc[j]);
        }
        float* gout = g_CtC + bs*RR*RR + r*RR + q*16;
        #pragma unroll
        for (int j = 0; j < 16; j++) atomicAdd(&gout[j], ctc[j]);
    }
}

// ---------- numB: dedicated 64-n-chunk 2-stage pipeline, coalesced 128B rows ----------
__global__ void __launch_bounds__(256, 2) k_numBmma(){
    extern __shared__ char sm[];
    uint32_t sb = smem_u32(sm);
    int bs = blockIdx.z, d0 = blockIdx.y*128, tid = threadIdx.x;
    size_t nb = (size_t)blockIdx.x * 2048;
    const bf16* Ah = g_xc_h + ((size_t)bs*DD + d0)*NN + nb;
    const bf16* Al = g_xc_l + ((size_t)bs*DD + d0)*NN + nb;
    const bf16* Bh = g_ct_h + ((size_t)bs*NN + nb)*RR;
    const bf16* Bl = g_ct_l + ((size_t)bs*NN + nb)*RR;
    int wid = tid >> 5, wm = wid >> 1, wn = wid & 1;

    AccFrag acc[2][2];
    #pragma unroll
    for (int i = 0; i < 2; i++)
        #pragma unroll
        for (int j = 0; j < 2; j++) wmma::fill_fragment(acc[i][j], 0.0f);

    auto issueN = [&](int st, size_t k0){
        uint32_t ab = sb + NST(st), bb = sb + NST(st) + 36864;
        #pragma unroll
        for (int u = 0; u < 4; u++){
            int idx = tid + u*256, r = idx >> 3, sg = (idx & 7)*8;
            cpa16(ab +         (r*72 + sg)*2, Ah + (size_t)r*NN + k0 + sg);
            cpa16(ab + 18432 + (r*72 + sg)*2, Al + (size_t)r*NN + k0 + sg);
        }
        #pragma unroll
        for (int u = 0; u < 2; u++){
            int idx = tid + u*256, n = idx >> 3, sg = (idx & 7)*8;
            cpa16(bb +        (n*72 + sg)*2, Bh + (k0 + n)*RR + sg);
            cpa16(bb + 9216 + (n*72 + sg)*2, Bl + (k0 + n)*RR + sg);
        }
        CPCOMMIT();
    };

    issueN(0, 0); issueN(1, 64);
    for (int kc = 0; kc < 32; kc++){
        CPWAIT1();                  // committed = 2+kc; chunks 0..kc complete
        __syncthreads();
        int cur = kc & 1;
        bf16* As = (bf16*)(sm + NST(cur));
        bf16* Asl = As + 9216;      // 18432 bytes = 9216 elements
        bf16* Bs = (bf16*)(sm + NST(cur) + 36864);
        bf16* Bsl = Bs + 4608;      // 9216 bytes
        #pragma unroll
        for (int k = 0; k < 4; k++){
            BFragR fbh[2], fbl[2];
            #pragma unroll
            for (int j = 0; j < 2; j++){
                wmma::load_matrix_sync(fbh[j], Bs  + (k*16)*72 + wn*32 + j*16, 72);
                wmma::load_matrix_sync(fbl[j], Bsl + (k*16)*72 + wn*32 + j*16, 72);
            }
            AFragR fah[2], fal[2];
            #pragma unroll
            for (int i = 0; i < 2; i++){
                wmma::load_matrix_sync(fah[i], As  + (wm*32+i*16)*72 + k*16, 72);
                wmma::load_matrix_sync(fal[i], Asl + (wm*32+i*16)*72 + k*16, 72);
            }
            #pragma unroll
            for (int i = 0; i < 2; i++)
                #pragma unroll
                for (int j = 0; j < 2; j++){
                    wmma::mma_sync(acc[i][j], fah[i], fbh[j], acc[i][j]);
                    wmma::mma_sync(acc[i][j], fah[i], fbl[j], acc[i][j]);
                    wmma::mma_sync(acc[i][j], fal[i], fbh[j], acc[i][j]);
                }
        }
        __syncthreads();
        if (kc + 2 < 32) issueN(cur, (size_t)(kc+2)*64);
        else CPCOMMIT();
    }
    store_acc(sm, acc, 72);
    __syncthreads();
    float* Ct = (float*)sm;
    int d = tid >> 1, h = tid & 1;
    float* out = g_numB + (bs*DD + d0 + d)*RR + h*32;
    #pragma unroll
    for (int j = 0; j < 32; j++) atomicAdd(&out[j], Ct[d*72 + h*32 + j]);
}

// ---------- b update (zeroes consumed accumulators) ----------
__global__ void __launch_bounds__(128) k_bupdate(int selIn, int selOut){
    int r = blockIdx.x, bs = blockIdx.y, tid = threadIdx.x;
    __shared__ float ctcCol[64], red[128];
    const float* bin = bsel(selIn) + bs*DD*RR;
    float* bout = bsel(selOut) + bs*DD*RR;
    float* nb = g_numB + bs*DD*RR;
    if (tid < 64) ctcCol[tid] = g_CtC[bs*RR*RR + tid*RR + r];
    __syncthreads();
    float v[4], ss = 0.f;
    #pragma unroll
    for (int q = 0; q < 4; q++){
        int d = tid + q*128; const float* brow = bin + d*RR;
        float den = EPSF;
        #pragma unroll 8
        for (int s = 0; s < RR; s++) den = fmaf(brow[s], ctcCol[s], den);
        float t = fmaxf(brow[r] * nb[d*RR + r] / den, EPSF);
        v[q] = t; ss += t*t;
        nb[d*RR + r] = 0.f;
    }
    red[tid] = ss; __syncthreads();
    for (int o = 64; o > 0; o >>= 1){ if (tid < o) red[tid] += red[tid+o]; __syncthreads(); }
    float inv = 1.f / fmaxf(sqrtf(red[0]), 1e-12f);
    #pragma unroll
    for (int q = 0; q < 4; q++){
        int d = tid + q*128;
        float w = v[q] * inv;
        bout[d*RR + r] = w;
        unsigned short h, l; split2(w, h, l);
        g_bt_h[(bs*RR+r)*DD + d] = __ushort_as_bfloat16(h);
        g_bt_l[(bs*RR+r)*DD + d] = __ushort_as_bfloat16(l);
        g_bn_h[(bs*DD+d)*RR + r] = __ushort_as_bfloat16(h);
        g_bn_l[(bs*DD+d)*RR + r] = __ushort_as_bfloat16(l);
    }
    if (tid < 64){
        g_CtC[bs*RR*RR + tid*RR + r] = 0.f;
        g_BtB[bs*RR*RR + r*64 + tid] = 0.f;
    }
}

// ---------- x_hat ----------
__global__ void __launch_bounds__(256, 2) k_xhat(float* __restrict__ out){
    extern __shared__ char sm[];
    uint32_t sb = smem_u32(sm);
    int bs = blockIdx.z, d0 = blockIdx.y*128, n0 = blockIdx.x*64, tid = threadIdx.x;
    AccFrag acc[2][2];
    gemm_core<false>(g_bn_h + (bs*DD + d0)*RR,         g_bn_l + (bs*DD + d0)*RR,         RR,
                     g_cn_h + ((size_t)bs*NN + n0)*RR, g_cn_l + ((size_t)bs*NN + n0)*RR, RR,
                     2, sm, sb, acc);
    __syncthreads();
    store_acc(sm, acc, 72);
    __syncthreads();
    float* Ct = (float*)sm;
    int d = tid >> 1, h = tid & 1;
    float* orow = out + (size_t)(bs*DD + d0 + d)*NN + n0 + h*32;
    #pragma unroll
    for (int j4 = 0; j4 < 32; j4 += 4)
        *(float4*)(orow + j4) = make_float4(Ct[d*72+h*32+j4], Ct[d*72+h*32+j4+1], Ct[d*72+h*32+j4+2], Ct[d*72+h*32+j4+3]);
}

// ---------- orchestration ----------
extern "C" void kernel_launch(void* const* d_in, const int* in_sizes, int n_in,
                              void* d_out, int out_size){
    const float* x = (const float*)d_in[0];
    const float* bases = (const float*)d_in[1];
    float* out = (float*)d_out;

    cudaFuncSetAttribute(k_cmma<0>, cudaFuncAttributeMaxDynamicSharedMemorySize, SMEMG);
    cudaFuncSetAttribute(k_cmma<1>, cudaFuncAttributeMaxDynamicSharedMemorySize, SMEMG);
    cudaFuncSetAttribute(k_cmma<2>, cudaFuncAttributeMaxDynamicSharedMemorySize, SMEMG);
    cudaFuncSetAttribute(k_numBmma, cudaFuncAttributeMaxDynamicSharedMemorySize, SMEMN);
    cudaFuncSetAttribute(k_xhat,    cudaFuncAttributeMaxDynamicSharedMemorySize, SMEMG);

    k_normb<<<BS*RR, 128>>>(bases);
    k_prep<<<16384, 256>>>(x);
    k_zero<<<256, 256>>>();
    k_btb<<<dim3(8, BS), 256>>>(0);
    k_cmma<0><<<dim3(NN/128, BS), 256, SMEMG>>>(0);
    int sel = 0;
    for (int step = 0; step < 6; step++){
        k_cmma<1><<<dim3(NN/128, BS), 256, SMEMG>>>(step > 0 ? 1 : 0);
        k_numBmma<<<dim3(32, DD/128, BS), 256, SMEMN>>>();
        k_bupdate<<<dim3(RR, BS), 128>>>(sel, 1 - sel);
        sel = 1 - sel;
        k_btb<<<dim3(8, BS), 256>>>(sel);
    }
    k_cmma<2><<<dim3(NN/128, BS), 256, SMEMG>>>(1);
    k_xhat<<<dim3(NN/64, DD/128, BS), 256, SMEMG>>>(out);
}

// round 17
// speedup vs baseline: 1.3738x; 1.2759x over previous
#include <cuda_runtime.h>
#include <cuda_fp16.h>
#include <mma.h>
#include <cstdint>
#include <math.h>
using namespace nvcuda;
typedef __half fp16;

#define BS 2
#define DD 512
#define NN 65536
#define RR 64
#define EPSF 1e-6f

// ---------- device scratch ----------
__device__ __align__(16) fp16 g_xu[(size_t)BS*DD*NN];                 // fp16(x) unclamped [d][n]
__device__ __align__(16) fp16 g_xc[(size_t)BS*DD*NN];                 // fp16(clamp(x)) [d][n]
__device__ __align__(16) fp16 g_ct_h[(size_t)BS*NN*RR], g_ct_l[(size_t)BS*NN*RR]; // c' h+l [n][r]
__device__ __align__(16) fp16 g_cn[(size_t)BS*NN*RR];                 // c_new single [n][r]
__device__ __align__(16) fp16 g_bt_h[BS*RR*DD], g_bt_l[BS*RR*DD];     // b^T h+l [r][d]
__device__ __align__(16) fp16 g_bn_h[BS*DD*RR], g_bn_l[BS*DD*RR];     // b h+l [d][r]
__device__ __align__(16) float g_c[(size_t)BS*NN*RR];
__device__ float g_b0[BS*DD*RR], g_b1[BS*DD*RR];
__device__ float g_BtB[BS*RR*RR], g_CtC[BS*RR*RR], g_numB[BS*DD*RR];
__device__ __forceinline__ float* bsel(int s){ return s ? g_b1 : g_b0; }

__device__ __forceinline__ void split2h(float v, unsigned short& h, unsigned short& l){
    fp16 hb = __float2half_rn(v);
    fp16 lb = __float2half_rn(v - __half2float(hb));
    h = __half_as_ushort(hb); l = __half_as_ushort(lb);
}
__device__ __forceinline__ uint32_t pk(unsigned short a, unsigned short b){ return (uint32_t)a | ((uint32_t)b << 16); }
__device__ __forceinline__ uint32_t smem_u32(const void* p){
    uint32_t a; asm("{ .reg .u64 t; cvta.to.shared.u64 t, %1; cvt.u32.u64 %0, t; }" : "=r"(a) : "l"(p)); return a;
}
__device__ __forceinline__ void cpa16(uint32_t s, const void* g){
    asm volatile("cp.async.cg.shared.global [%0], [%1], 16;" :: "r"(s), "l"(g) : "memory");
}
#define CPCOMMIT() asm volatile("cp.async.commit_group;" ::: "memory")
#define CPWAIT0()  asm volatile("cp.async.wait_group 0;" ::: "memory")
#define CPWAIT1()  asm volatile("cp.async.wait_group 1;" ::: "memory")
#define CPWAIT2()  asm volatile("cp.async.wait_group 2;" ::: "memory")

// cmma smem: 3 stages x 18944 (A 8704 | Bh 5120 | Bl 5120) = 56832
// overlays: Ct f32[128][76] @0 (38912), BtB @40960 (16384), csm f32[128][65] @57344 (33280)
#define ASTC(st) ((st)*18944)
#define BT_OFF  40960
#define CSM_OFF 57344
#define SMEMG 90624
#define CTS 76
// numB smem: 2 stages x 36864 (A 18432 | Bh 9216 | Bl 9216)
#define NSTN(st) ((st)*36864)
#define SMEMN 73728
// xhat smem: A_h 18432 | A_l 18432 | B 9216 = 46080 (Ct overlay 36864 fits)
#define SMEMX 46080

typedef wmma::fragment<wmma::accumulator,16,16,16,float> AccFrag;
typedef wmma::fragment<wmma::matrix_a,16,16,16,fp16,wmma::row_major> AFragR;
typedef wmma::fragment<wmma::matrix_a,16,16,16,fp16,wmma::col_major> AFragC;
typedef wmma::fragment<wmma::matrix_b,16,16,16,fp16,wmma::row_major> BFragR;
typedef wmma::fragment<wmma::matrix_b,16,16,16,fp16,wmma::col_major> BFragC;

__device__ __forceinline__ void store_acc(char* sm, AccFrag (&acc)[2][2], int ldm){
    float* Ct = (float*)sm;
    int wid = threadIdx.x >> 5, wm = wid >> 1, wn = wid & 1;
    #pragma unroll
    for (int i = 0; i < 2; i++)
        #pragma unroll
        for (int j = 0; j < 2; j++)
            wmma::store_matrix_sync(Ct + (wm*32+i*16)*ldm + wn*32+j*16, acc[i][j], ldm, wmma::mem_row_major);
}

// ---------- prep: single fp16 copies of x ----------
__global__ void __launch_bounds__(256) k_prep(const float* __restrict__ x){
    size_t base = ((size_t)blockIdx.x*256 + threadIdx.x)*16;
    #pragma unroll
    for (int q = 0; q < 4; q++){
        size_t o = base + q*4;
        float4 v = *(const float4*)(x + o);
        unsigned short u0 = __half_as_ushort(__float2half_rn(v.x));
        unsigned short u1 = __half_as_ushort(__float2half_rn(v.y));
        unsigned short u2 = __half_as_ushort(__float2half_rn(v.z));
        unsigned short u3 = __half_as_ushort(__float2half_rn(v.w));
        *(uint2*)(g_xu + o) = make_uint2(pk(u0,u1), pk(u2,u3));
        u0 = __half_as_ushort(__float2half_rn(fmaxf(v.x,EPSF)));
        u1 = __half_as_ushort(__float2half_rn(fmaxf(v.y,EPSF)));
        u2 = __half_as_ushort(__float2half_rn(fmaxf(v.z,EPSF)));
        u3 = __half_as_ushort(__float2half_rn(fmaxf(v.w,EPSF)));
        *(uint2*)(g_xc + o) = make_uint2(pk(u0,u1), pk(u2,u3));
    }
}

__global__ void __launch_bounds__(128) k_normb(const float* __restrict__ bases){
    int bs = blockIdx.x >> 6, r = blockIdx.x & 63, tid = threadIdx.x;
    __shared__ float red[128];
    float s = 0.f;
    for (int d = tid; d < DD; d += 128){ float v = bases[(bs*DD+d)*RR + r]; s += v*v; }
    red[tid] = s; __syncthreads();
    for (int o = 64; o > 0; o >>= 1){ if (tid < o) red[tid] += red[tid+o]; __syncthreads(); }
    float inv = 1.f / fmaxf(sqrtf(red[0]), 1e-12f);
    for (int d = tid; d < DD; d += 128){
        float v = bases[(bs*DD+d)*RR + r] * inv;
        g_b0[(bs*DD+d)*RR + r] = v;
        unsigned short h, l; split2h(v, h, l);
        g_bt_h[(bs*RR+r)*DD + d] = __ushort_as_half(h);
        g_bt_l[(bs*RR+r)*DD + d] = __ushort_as_half(l);
    }
}

__global__ void k_zero(){
    int i = blockIdx.x*256 + threadIdx.x;
    if (i < BS*RR*RR){ g_BtB[i] = 0.f; g_CtC[i] = 0.f; }
    if (i < BS*DD*RR) g_numB[i] = 0.f;
}

__global__ void __launch_bounds__(256) k_btb(int sel){
    __shared__ float bsh[64][65];
    int bs = blockIdx.y, d0 = blockIdx.x*64, tid = threadIdx.x;
    const float* bb = bsel(sel) + bs*DD*RR + d0*RR;
    for (int i = tid*4; i < 4096; i += 1024){
        float4 v = *(const float4*)(bb + i);
        int d = i >> 6, r = i & 63;
        bsh[d][r]=v.x; bsh[d][r+1]=v.y; bsh[d][r+2]=v.z; bsh[d][r+3]=v.w;
    }
    __syncthreads();
    int r = tid & 63, sq = (tid >> 6)*16;
    float acc[16];
    #pragma unroll
    for (int j = 0; j < 16; j++) acc[j] = 0.f;
    for (int d = 0; d < 64; d++){
        float br = bsh[d][r];
        #pragma unroll
        for (int j = 0; j < 16; j++) acc[j] = fmaf(br, bsh[d][sq+j], acc[j]);
    }
    float* o = g_BtB + bs*RR*RR + r*RR + sq;
    #pragma unroll
    for (int j = 0; j < 16; j++) atomicAdd(&o[j], acc[j]);
}

// ---------- fused c kernel: MODE 0 init softmax, 1 MU step, 2 final ----------
template<int MODE>
__global__ void __launch_bounds__(256, 2) k_cmma(int clampc){
    extern __shared__ char sm[];
    uint32_t sb = smem_u32(sm);
    int bs = blockIdx.y, n0 = blockIdx.x*128, tid = threadIdx.x;
    const fp16* xa = (MODE==0 ? g_xu : g_xc) + (size_t)bs*DD*NN + n0;
    const fp16* Bh = g_bt_h + bs*RR*DD;
    const fp16* Bl = g_bt_l + bs*RR*DD;
    int wid = tid >> 5, wm = wid >> 1, wn = wid & 1;

    AccFrag acc[2][2];
    #pragma unroll
    for (int i = 0; i < 2; i++)
        #pragma unroll
        for (int j = 0; j < 2; j++) wmma::fill_fragment(acc[i][j], 0.0f);

    auto issueC = [&](int st, size_t k0){
        uint32_t ab = sb + ASTC(st), bb = ab + 8704;
        #pragma unroll
        for (int u = 0; u < 2; u++){
            int idx = tid + u*256, r = idx >> 4, sg = (idx & 15)*8;
            cpa16(ab + (r*136 + sg)*2, xa + (k0+r)*NN + sg);
        }
        { int r = tid >> 2, sg = (tid & 3)*8;
          cpa16(bb +        (r*40 + sg)*2, Bh + r*DD + k0 + sg);
          cpa16(bb + 5120 + (r*40 + sg)*2, Bl + r*DD + k0 + sg);
        }
        CPCOMMIT();
    };
    issueC(0, 0); issueC(1, 32); issueC(2, 64);
    for (int kc = 0; kc < 16; kc++){
        CPWAIT2();
        __syncthreads();
        int cur = kc % 3;
        fp16* As  = (fp16*)(sm + ASTC(cur));
        fp16* Bs  = (fp16*)(sm + ASTC(cur) + 8704);
        fp16* Bsl = Bs + 2560;
        #pragma unroll
        for (int k = 0; k < 2; k++){
            BFragC fbh[2], fbl[2];
            #pragma unroll
            for (int j = 0; j < 2; j++){
                wmma::load_matrix_sync(fbh[j], Bs  + (wn*32+j*16)*40 + k*16, 40);
                wmma::load_matrix_sync(fbl[j], Bsl + (wn*32+j*16)*40 + k*16, 40);
            }
            AFragC fa[2];
            #pragma unroll
            for (int i = 0; i < 2; i++)
                wmma::load_matrix_sync(fa[i], As + (k*16)*136 + wm*32+i*16, 136);
            #pragma unroll
            for (int i = 0; i < 2; i++)
                #pragma unroll
                for (int j = 0; j < 2; j++){
                    wmma::mma_sync(acc[i][j], fa[i], fbh[j], acc[i][j]);
                    wmma::mma_sync(acc[i][j], fa[i], fbl[j], acc[i][j]);
                }
        }
        __syncthreads();
        if (kc + 3 < 16) issueC(cur, (size_t)(kc+3)*32);
        else CPCOMMIT();
    }
    __syncthreads();
    store_acc(sm, acc, CTS);
    float* Ct  = (float*)sm;
    float* Bt  = (float*)(sm + BT_OFF);
    float* csm = (float*)(sm + CSM_OFF);
    if (MODE != 0){
        for (int i = tid; i < RR*RR; i += 256) Bt[i] = g_BtB[bs*RR*RR + i];
        size_t cbase = ((size_t)bs*NN + n0)*RR;
        for (int i = tid; i < 2048; i += 256){
            int n = i >> 4, r4 = (i & 15)*4;
            float4 v = *(const float4*)(g_c + cbase + n*RR + r4);
            if (clampc){ v.x=fmaxf(v.x,EPSF); v.y=fmaxf(v.y,EPSF); v.z=fmaxf(v.z,EPSF); v.w=fmaxf(v.w,EPSF); }
            csm[n*65+r4]=v.x; csm[n*65+r4+1]=v.y; csm[n*65+r4+2]=v.z; csm[n*65+r4+3]=v.w;
        }
    }
    __syncthreads();

    int n = tid >> 1, h = tid & 1;
    size_t crow = ((size_t)bs*NN + n0 + n)*RR;
    if (MODE == 0){
        float v[32], m = -1e30f;
        #pragma unroll
        for (int j = 0; j < 32; j++){ v[j] = Ct[n*CTS + h*32 + j]; m = fmaxf(m, v[j]); }
        m = fmaxf(m, __shfl_xor_sync(0xffffffffu, m, 1));
        float s = 0.f;
        #pragma unroll
        for (int j = 0; j < 32; j++){ v[j] = __expf(v[j]-m); s += v[j]; }
        s += __shfl_xor_sync(0xffffffffu, s, 1);
        float inv = 1.f/s;
        #pragma unroll
        for (int j4 = 0; j4 < 32; j4 += 4)
            *(float4*)(g_c + crow + h*32 + j4) = make_float4(v[j4]*inv, v[j4+1]*inv, v[j4+2]*inv, v[j4+3]*inv);
        return;
    }
    float den[32];
    #pragma unroll
    for (int j = 0; j < 32; j++) den[j] = 0.f;
    #pragma unroll 8
    for (int s = 0; s < 64; s++){
        float cv = csm[n*65 + s];
        const float* row = &Bt[s*64 + h*32];
        #pragma unroll
        for (int j = 0; j < 32; j++) den[j] = fmaf(cv, row[j], den[j]);
    }
    #pragma unroll
    for (int j4 = 0; j4 < 32; j4 += 4){
        float cp[4];
        #pragma unroll
        for (int t = 0; t < 4; t++){
            int j = j4 + t;
            cp[t] = csm[n*65 + h*32 + j] * Ct[n*CTS + h*32 + j] / (den[j] + EPSF);
            Ct[n*CTS + h*32 + j] = cp[t];
        }
        size_t o = crow + h*32 + j4;
        if (MODE == 1){
            *(float4*)(g_c + crow + h*32 + j4) = make_float4(cp[0], cp[1], cp[2], cp[3]);
            unsigned short hh[4], ll[4];
            #pragma unroll
            for (int t = 0; t < 4; t++) split2h(cp[t], hh[t], ll[t]);
            *(uint2*)(g_ct_h + o) = make_uint2(pk(hh[0],hh[1]), pk(hh[2],hh[3]));
            *(uint2*)(g_ct_l + o) = make_uint2(pk(ll[0],ll[1]), pk(ll[2],ll[3]));
        } else {
            unsigned short hh[4];
            #pragma unroll
            for (int t = 0; t < 4; t++) hh[t] = __half_as_ushort(__float2half_rn(cp[t]));
            *(uint2*)(g_cn + o) = make_uint2(pk(hh[0],hh[1]), pk(hh[2],hh[3]));
        }
    }
    if (MODE == 2) return;
    __syncthreads();
    {   // CtC partials
        int r = tid & 63, q = tid >> 6;
        float ctc[16];
        #pragma unroll
        for (int j = 0; j < 16; j++) ctc[j] = 0.f;
        for (int nn2 = 0; nn2 < 128; nn2++){
            float cr = Ct[nn2*CTS + r];
            const float* row = &Ct[nn2*CTS + q*16];
            #pragma unroll
            for (int j = 0; j < 16; j++) ctc[j] = fmaf(cr, row[j], ctc[j]);
        }
        float* gout = g_CtC + bs*RR*RR + r*RR + q*16;
        #pragma unroll
        for (int j = 0; j < 16; j++) atomicAdd(&gout[j], ctc[j]);
    }
}

// ---------- numB: A = xc single, B = ct h+l, 64-n chunks, 2 stages ----------
__global__ void __launch_bounds__(256, 3) k_numBmma(){
    extern __shared__ char sm[];
    uint32_t sb = smem_u32(sm);
    int bs = blockIdx.z, d0 = blockIdx.y*128, tid = threadIdx.x;
    size_t nb = (size_t)blockIdx.x * 2048;
    const fp16* Ah = g_xc + ((size_t)bs*DD + d0)*NN + nb;
    const fp16* Bh = g_ct_h + ((size_t)bs*NN + nb)*RR;
    const fp16* Bl = g_ct_l + ((size_t)bs*NN + nb)*RR;
    int wid = tid >> 5, wm = wid >> 1, wn = wid & 1;

    AccFrag acc[2][2];
    #pragma unroll
    for (int i = 0; i < 2; i++)
        #pragma unroll
        for (int j = 0; j < 2; j++) wmma::fill_fragment(acc[i][j], 0.0f);

    auto issueN = [&](int st, size_t k0){
        uint32_t ab = sb + NSTN(st), bb = ab + 18432;
        #pragma unroll
        for (int u = 0; u < 4; u++){
            int idx = tid + u*256, r = idx >> 3, sg = (idx & 7)*8;
            cpa16(ab + (r*72 + sg)*2, Ah + (size_t)r*NN + k0 + sg);
        }
        #pragma unroll
        for (int u = 0; u < 2; u++){
            int idx = tid + u*256, n = idx >> 3, sg = (idx & 7)*8;
            cpa16(bb +        (n*72 + sg)*2, Bh + (k0 + n)*RR + sg);
            cpa16(bb + 9216 + (n*72 + sg)*2, Bl + (k0 + n)*RR + sg);
        }
        CPCOMMIT();
    };
    issueN(0, 0); issueN(1, 64);
    for (int kc = 0; kc < 32; kc++){
        CPWAIT1();
        __syncthreads();
        int cur = kc & 1;
        fp16* As  = (fp16*)(sm + NSTN(cur));
        fp16* Bs  = (fp16*)(sm + NSTN(cur) + 18432);
        fp16* Bsl = Bs + 4608;
        #pragma unroll
        for (int k = 0; k < 4; k++){
            BFragR fbh[2], fbl[2];
            #pragma unroll
            for (int j = 0; j < 2; j++){
                wmma::load_matrix_sync(fbh[j], Bs  + (k*16)*72 + wn*32 + j*16, 72);
                wmma::load_matrix_sync(fbl[j], Bsl + (k*16)*72 + wn*32 + j*16, 72);
            }
            AFragR fa[2];
            #pragma unroll
            for (int i = 0; i < 2; i++)
                wmma::load_matrix_sync(fa[i], As + (wm*32+i*16)*72 + k*16, 72);
            #pragma unroll
            for (int i = 0; i < 2; i++)
                #pragma unroll
                for (int j = 0; j < 2; j++){
                    wmma::mma_sync(acc[i][j], fa[i], fbh[j], acc[i][j]);
                    wmma::mma_sync(acc[i][j], fa[i], fbl[j], acc[i][j]);
                }
        }
        __syncthreads();
        if (kc + 2 < 32) issueN(cur, (size_t)(kc+2)*64);
        else CPCOMMIT();
    }
    store_acc(sm, acc, 72);
    __syncthreads();
    float* Ct = (float*)sm;
    int d = tid >> 1, h = tid & 1;
    float* out = g_numB + (bs*DD + d0 + d)*RR + h*32;
    #pragma unroll
    for (int j = 0; j < 32; j++) atomicAdd(&out[j], Ct[d*72 + h*32 + j]);
}

// ---------- b update (zeroes consumed accumulators) ----------
__global__ void __launch_bounds__(128) k_bupdate(int selIn, int selOut){
    int r = blockIdx.x, bs = blockIdx.y, tid = threadIdx.x;
    __shared__ float ctcCol[64], red[128];
    const float* bin = bsel(selIn) + bs*DD*RR;
    float* bout = bsel(selOut) + bs*DD*RR;
    float* nb = g_numB + bs*DD*RR;
    if (tid < 64) ctcCol[tid] = g_CtC[bs*RR*RR + tid*RR + r];
    __syncthreads();
    float v[4], ss = 0.f;
    #pragma unroll
    for (int q = 0; q < 4; q++){
        int d = tid + q*128; const float* brow = bin + d*RR;
        float den = EPSF;
        #pragma unroll 8
        for (int s = 0; s < RR; s++) den = fmaf(brow[s], ctcCol[s], den);
        float t = fmaxf(brow[r] * nb[d*RR + r] / den, EPSF);
        v[q] = t; ss += t*t;
        nb[d*RR + r] = 0.f;
    }
    red[tid] = ss; __syncthreads();
    for (int o = 64; o > 0; o >>= 1){ if (tid < o) red[tid] += red[tid+o]; __syncthreads(); }
    float inv = 1.f / fmaxf(sqrtf(red[0]), 1e-12f);
    #pragma unroll
    for (int q = 0; q < 4; q++){
        int d = tid + q*128;
        float w = v[q] * inv;
        bout[d*RR + r] = w;
        unsigned short h, l; split2h(w, h, l);
        g_bt_h[(bs*RR+r)*DD + d] = __ushort_as_half(h);
        g_bt_l[(bs*RR+r)*DD + d] = __ushort_as_half(l);
        g_bn_h[(bs*DD+d)*RR + r] = __ushort_as_half(h);
        g_bn_l[(bs*DD+d)*RR + r] = __ushort_as_half(l);
    }
    if (tid < 64){
        g_CtC[bs*RR*RR + tid*RR + r] = 0.f;
        g_BtB[bs*RR*RR + r*64 + tid] = 0.f;
    }
}

// ---------- x_hat: A = bn h+l, B = cn single, K=64 one-shot ----------
__global__ void __launch_bounds__(256, 2) k_xhat(float* __restrict__ out){
    extern __shared__ char sm[];
    uint32_t sb = smem_u32(sm);
    int bs = blockIdx.z, d0 = blockIdx.y*128, n0 = blockIdx.x*64, tid = threadIdx.x;
    int wid = tid >> 5, wm = wid >> 1, wn = wid & 1;
    const fp16* Ah = g_bn_h + (size_t)(bs*DD + d0)*RR;
    const fp16* Al = g_bn_l + (size_t)(bs*DD + d0)*RR;
    const fp16* Bp = g_cn + ((size_t)bs*NN + n0)*RR;
    #pragma unroll
    for (int u = 0; u < 4; u++){
        int idx = tid + u*256, r = idx >> 3, sg = (idx & 7)*8;
        cpa16(sb +         (r*72 + sg)*2, Ah + (size_t)r*RR + sg);
        cpa16(sb + 18432 + (r*72 + sg)*2, Al + (size_t)r*RR + sg);
    }
    #pragma unroll
    for (int u = 0; u < 2; u++){
        int idx = tid + u*256, n = idx >> 3, sg = (idx & 7)*8;
        cpa16(sb + 36864 + (n*72 + sg)*2, Bp + (size_t)n*RR + sg);
    }
    CPCOMMIT(); CPWAIT0();
    __syncthreads();
    fp16* As  = (fp16*)sm;
    fp16* Asl = As + 9216;
    fp16* Bs  = (fp16*)(sm + 36864);
    AccFrag acc[2][2];
    #pragma unroll
    for (int i = 0; i < 2; i++)
        #pragma unroll
        for (int j = 0; j < 2; j++) wmma::fill_fragment(acc[i][j], 0.0f);
    #pragma unroll
    for (int k = 0; k < 4; k++){
        BFragC fb[2];
        #pragma unroll
        for (int j = 0; j < 2; j++)
            wmma::load_matrix_sync(fb[j], Bs + (wn*32+j*16)*72 + k*16, 72);
        AFragR fh[2], fl[2];
        #pragma unroll
        for (int i = 0; i < 2; i++){
            wmma::load_matrix_sync(fh[i], As  + (wm*32+i*16)*72 + k*16, 72);
            wmma::load_matrix_sync(fl[i], Asl + (wm*32+i*16)*72 + k*16, 72);
        }
        #pragma unroll
        for (int i = 0; i < 2; i++)
            #pragma unroll
            for (int j = 0; j < 2; j++){
                wmma::mma_sync(acc[i][j], fh[i], fb[j], acc[i][j]);
                wmma::mma_sync(acc[i][j], fl[i], fb[j], acc[i][j]);
            }
    }
    __syncthreads();
    store_acc(sm, acc, 72);
    __syncthreads();
    float* Ct = (float*)sm;
    int d = tid >> 1, h = tid & 1;
    float* orow = out + (size_t)(bs*DD + d0 + d)*NN + n0 + h*32;
    #pragma unroll
    for (int j4 = 0; j4 < 32; j4 += 4)
        *(float4*)(orow + j4) = make_float4(Ct[d*72+h*32+j4], Ct[d*72+h*32+j4+1], Ct[d*72+h*32+j4+2], Ct[d*72+h*32+j4+3]);
}

// ---------- orchestration ----------
extern "C" void kernel_launch(void* const* d_in, const int* in_sizes, int n_in,
                              void* d_out, int out_size){
    const float* x = (const float*)d_in[0];
    const float* bases = (const float*)d_in[1];
    float* out = (float*)d_out;

    cudaFuncSetAttribute(k_cmma<0>, cudaFuncAttributeMaxDynamicSharedMemorySize, SMEMG);
    cudaFuncSetAttribute(k_cmma<1>, cudaFuncAttributeMaxDynamicSharedMemorySize, SMEMG);
    cudaFuncSetAttribute(k_cmma<2>, cudaFuncAttributeMaxDynamicSharedMemorySize, SMEMG);
    cudaFuncSetAttribute(k_numBmma, cudaFuncAttributeMaxDynamicSharedMemorySize, SMEMN);
    cudaFuncSetAttribute(k_xhat,    cudaFuncAttributeMaxDynamicSharedMemorySize, SMEMX);

    k_normb<<<BS*RR, 128>>>(bases);
    k_prep<<<16384, 256>>>(x);
    k_zero<<<256, 256>>>();
    k_btb<<<dim3(8, BS), 256>>>(0);
    k_cmma<0><<<dim3(NN/128, BS), 256, SMEMG>>>(0);
    int sel = 0;
    for (int step = 0; step < 6; step++){
        k_cmma<1><<<dim3(NN/128, BS), 256, SMEMG>>>(step > 0 ? 1 : 0);
        k_numBmma<<<dim3(32, DD/128, BS), 256, SMEMN>>>();
        k_bupdate<<<dim3(RR, BS), 128>>>(sel, 1 - sel);
        sel = 1 - sel;
        k_btb<<<dim3(8, BS), 256>>>(sel);
    }
    k_cmma<2><<<dim3(NN/128, BS), 256, SMEMG>>>(1);
    k_xhat<<<dim3(NN/64, DD/128, BS), 256, SMEMX>>>(out);
}